// round 3
// baseline (speedup 1.0000x reference)
#include <cuda_runtime.h>
#include <cuda_bf16.h>
#include <cstdint>

// ---------------- problem dims ----------------
#define TT 2048
#define BB 16
#define DDIM 1024
#define MM (TT*BB)            // 32768 rows
#define SBD (BB*DDIM)         // 16384 lanes in scan
#define NELEM ((size_t)MM*DDIM)

// ---------------- device scratch (no cudaMalloc allowed) ----------------
__device__ __nv_bfloat16 g_xhi[NELEM];
__device__ __nv_bfloat16 g_xlo[NELEM];
__device__ __nv_bfloat16 g_whi[2*DDIM*DDIM];
__device__ __nv_bfloat16 g_wlo[2*DDIM*DDIM];
__device__ float g_alpha[NELEM];
__device__ float g_vraw[NELEM];

// ---------------- PTX helpers (base sm_103 target only: no tcgen05/TMA) ----
__device__ __forceinline__ uint32_t smem_u32(const void* p) {
    uint32_t a;
    asm("{ .reg .u64 t; cvta.to.shared.u64 t, %1; cvt.u32.u64 %0, t; }" : "=r"(a) : "l"(p));
    return a;
}
__device__ __forceinline__ void cp16(uint32_t s, const void* g) {
    asm volatile("cp.async.cg.shared.global [%0], [%1], 16;" :: "r"(s), "l"(g));
}
__device__ __forceinline__ void cp_commit() {
    asm volatile("cp.async.commit_group;" ::: "memory");
}
template <int N>
__device__ __forceinline__ void cp_wait() {
    asm volatile("cp.async.wait_group %0;" :: "n"(N) : "memory");
}
__device__ __forceinline__ void ldsm4(uint32_t* r, uint32_t addr) {
    asm volatile("ldmatrix.sync.aligned.m8n8.x4.shared.b16 {%0,%1,%2,%3}, [%4];"
                 : "=r"(r[0]), "=r"(r[1]), "=r"(r[2]), "=r"(r[3]) : "r"(addr));
}
__device__ __forceinline__ void mma16816(float* c, const uint32_t* a, const uint32_t* b) {
    asm volatile("mma.sync.aligned.m16n8k16.row.col.f32.bf16.bf16.f32 "
                 "{%0,%1,%2,%3}, {%4,%5,%6,%7}, {%8,%9}, {%0,%1,%2,%3};"
                 : "+f"(c[0]), "+f"(c[1]), "+f"(c[2]), "+f"(c[3])
                 : "r"(a[0]), "r"(a[1]), "r"(a[2]), "r"(a[3]), "r"(b[0]), "r"(b[1]));
}

// ---------------- split kernels (fp32 -> bf16 hi/lo) ----------------
__global__ void split_x_kernel(const float* __restrict__ x) {
    size_t i = (size_t)blockIdx.x * blockDim.x + threadIdx.x;  // float4 index
    if (i >= NELEM / 4) return;
    float4 v = reinterpret_cast<const float4*>(x)[i];
    union { __nv_bfloat16 b[4]; uint2 u; } H, L;
    float f[4] = {v.x, v.y, v.z, v.w};
#pragma unroll
    for (int j = 0; j < 4; j++) {
        __nv_bfloat16 h = __float2bfloat16(f[j]);
        H.b[j] = h;
        L.b[j] = __float2bfloat16(f[j] - __bfloat162float(h));
    }
    reinterpret_cast<uint2*>(g_xhi)[i] = H.u;
    reinterpret_cast<uint2*>(g_xlo)[i] = L.u;
}

__global__ void split_w_kernel(const float* __restrict__ Wa, const float* __restrict__ Wx) {
    size_t i = (size_t)blockIdx.x * blockDim.x + threadIdx.x;  // float4 index over 2 matrices
    const size_t nper = (size_t)DDIM * DDIM / 4;
    if (i >= 2 * nper) return;
    const float* src = (i < nper) ? Wa : Wx;
    size_t j = (i < nper) ? i : i - nper;
    float4 v = reinterpret_cast<const float4*>(src)[j];
    union { __nv_bfloat16 b[4]; uint2 u; } H, L;
    float f[4] = {v.x, v.y, v.z, v.w};
#pragma unroll
    for (int k = 0; k < 4; k++) {
        __nv_bfloat16 h = __float2bfloat16(f[k]);
        H.b[k] = h;
        L.b[k] = __float2bfloat16(f[k] - __bfloat162float(h));
    }
    reinterpret_cast<uint2*>(g_whi)[i] = H.u;
    reinterpret_cast<uint2*>(g_wlo)[i] = L.u;
}

// ---------------- GEMM: out[m,e] = act( sum_d x[m,d]*W[e,d] + bias[e] ) ------
// bf16x3 via mma.sync m16n8k16 (HMMA). CTA tile 128x256x32, 512 thr, 2-stage cp.async.
// smem per stage: Ahi,Alo [128][32] + Bhi,Blo [256][32], padded rows (40 bf16 = 80B).
static constexpr int BK       = 32;
static constexpr int ROWB     = 80;          // padded row bytes (32 bf16 + 16B pad)
static constexpr int A_TILE_B = 128 * ROWB;  // 10240
static constexpr int B_TILE_B = 256 * ROWB;  // 20480
static constexpr int ST_AHI = 0;
static constexpr int ST_ALO = ST_AHI + A_TILE_B;
static constexpr int ST_BHI = ST_ALO + A_TILE_B;
static constexpr int ST_BLO = ST_BHI + B_TILE_B;
static constexpr int STAGE_B  = ST_BLO + B_TILE_B;          // 61440
static constexpr int SMEM_GEMM_TOTAL = 2 * STAGE_B;         // 122880

__global__ void __launch_bounds__(512, 1)
gemm_kernel(const float* __restrict__ b_alpha, const float* __restrict__ b_v) {
    extern __shared__ char smem[];
    const uint32_t sbase = smem_u32(smem);
    const int tid = threadIdx.x;
    const int wid = tid >> 5;
    const int l   = tid & 31;
    const int wid_m = wid >> 3;      // 0..1  (64-row slabs)
    const int wid_n = wid & 7;       // 0..7  (32-col slabs)
    const int bn = blockIdx.x;       // 0..3   (N tiles of 256)
    const int bm = blockIdx.y;       // 0..255 (M tiles of 128)
    const int ws = blockIdx.z;       // 0: alpha, 1: vraw

    const __nv_bfloat16* __restrict__ Ahi_g = g_xhi + (size_t)bm * 128 * DDIM;
    const __nv_bfloat16* __restrict__ Alo_g = g_xlo + (size_t)bm * 128 * DDIM;
    const __nv_bfloat16* __restrict__ Bhi_g = g_whi + (size_t)ws * DDIM * DDIM + (size_t)bn * 256 * DDIM;
    const __nv_bfloat16* __restrict__ Blo_g = g_wlo + (size_t)ws * DDIM * DDIM + (size_t)bn * 256 * DDIM;
    float* __restrict__ outp = ws ? g_vraw : g_alpha;
    const float* __restrict__ bias = ws ? b_v : b_alpha;

    // cp.async mapping: A tiles: 512 chunks each (1/thread); B tiles: 1024 (2/thread)
    const int a_row = tid >> 2, a_seg = tid & 3;
    const int b_row0 = tid >> 2, b_row1 = (tid + 512) >> 2;

    auto issue_stage = [&](int stage, int kc) {
        const uint32_t s0 = sbase + stage * STAGE_B;
        const size_t kel = (size_t)kc * BK;
        cp16(s0 + ST_AHI + a_row * ROWB + a_seg * 16, Ahi_g + (size_t)a_row * DDIM + kel + a_seg * 8);
        cp16(s0 + ST_ALO + a_row * ROWB + a_seg * 16, Alo_g + (size_t)a_row * DDIM + kel + a_seg * 8);
        cp16(s0 + ST_BHI + b_row0 * ROWB + a_seg * 16, Bhi_g + (size_t)b_row0 * DDIM + kel + a_seg * 8);
        cp16(s0 + ST_BHI + b_row1 * ROWB + a_seg * 16, Bhi_g + (size_t)b_row1 * DDIM + kel + a_seg * 8);
        cp16(s0 + ST_BLO + b_row0 * ROWB + a_seg * 16, Blo_g + (size_t)b_row0 * DDIM + kel + a_seg * 8);
        cp16(s0 + ST_BLO + b_row1 * ROWB + a_seg * 16, Blo_g + (size_t)b_row1 * DDIM + kel + a_seg * 8);
        cp_commit();
    };

    // ldmatrix lane-address components
    const uint32_t a_lane_off = (uint32_t)((l & 15) * ROWB + (l >> 4) * 16);
    const uint32_t b_lane_off = (uint32_t)(((l & 7) + ((l >> 4) << 3)) * ROWB + ((l >> 3) & 1) * 16);

    float acc[4][4][4];
#pragma unroll
    for (int mi = 0; mi < 4; mi++)
#pragma unroll
        for (int ni = 0; ni < 4; ni++)
#pragma unroll
            for (int r = 0; r < 4; r++) acc[mi][ni][r] = 0.0f;

    issue_stage(0, 0);

#pragma unroll 1
    for (int kc = 0; kc < DDIM / BK; kc++) {
        if (kc + 1 < DDIM / BK) { issue_stage((kc + 1) & 1, kc + 1); cp_wait<1>(); }
        else                    { cp_wait<0>(); }
        __syncthreads();

        const uint32_t s0 = sbase + (kc & 1) * STAGE_B;
        const uint32_t sAhi = s0 + ST_AHI + (uint32_t)(wid_m * 64 * ROWB) + a_lane_off;
        const uint32_t sAlo = s0 + ST_ALO + (uint32_t)(wid_m * 64 * ROWB) + a_lane_off;
        const uint32_t sBhi = s0 + ST_BHI + (uint32_t)(wid_n * 32 * ROWB) + b_lane_off;
        const uint32_t sBlo = s0 + ST_BLO + (uint32_t)(wid_n * 32 * ROWB) + b_lane_off;

#pragma unroll
        for (int ks = 0; ks < 2; ks++) {
            uint32_t bh[2][4], bl[2][4];
#pragma unroll
            for (int ni2 = 0; ni2 < 2; ni2++) {
                ldsm4(bh[ni2], sBhi + ni2 * 16 * ROWB + ks * 32);
                ldsm4(bl[ni2], sBlo + ni2 * 16 * ROWB + ks * 32);
            }
#pragma unroll
            for (int mi = 0; mi < 4; mi++) {
                uint32_t ah[4], al[4];
                ldsm4(ah, sAhi + mi * 16 * ROWB + ks * 32);
                ldsm4(al, sAlo + mi * 16 * ROWB + ks * 32);
#pragma unroll
                for (int n8 = 0; n8 < 4; n8++) {
                    const uint32_t* bhp = &bh[n8 >> 1][(n8 & 1) * 2];
                    const uint32_t* blp = &bl[n8 >> 1][(n8 & 1) * 2];
                    mma16816(acc[mi][n8], ah, bhp);
                    mma16816(acc[mi][n8], ah, blp);
                    mma16816(acc[mi][n8], al, bhp);
                }
            }
        }
        __syncthreads();
    }

    // epilogue: bias + activation, direct float2 stores
    const int row_base = bm * 128 + wid_m * 64 + (l >> 2);
    const int col_base = bn * 256 + wid_n * 32 + (l & 3) * 2;
#pragma unroll
    for (int mi = 0; mi < 4; mi++) {
#pragma unroll
        for (int n8 = 0; n8 < 4; n8++) {
            const int col = col_base + n8 * 8;
            const float bia0 = __ldg(&bias[col]);
            const float bia1 = __ldg(&bias[col + 1]);
#pragma unroll
            for (int half = 0; half < 2; half++) {
                const int row = row_base + mi * 16 + half * 8;
                float v0 = acc[mi][n8][half * 2 + 0] + bia0;
                float v1 = acc[mi][n8][half * 2 + 1] + bia1;
                float2 o;
                if (ws) { o.x = tanhf(v0); o.y = tanhf(v1); }
                else {
                    o.x = __fdividef(1.0f, 1.0f + __expf(-v0));
                    o.y = __fdividef(1.0f, 1.0f + __expf(-v1));
                }
                *reinterpret_cast<float2*>(outp + (size_t)row * DDIM + col) = o;
            }
        }
    }
}

// ---------------- scan kernel: 16384 independent recurrences over T ----------
__global__ void __launch_bounds__(128)
scan_kernel(const float* __restrict__ d_g, const float* __restrict__ b_g,
            float* __restrict__ out) {
    const int idx = blockIdx.x * blockDim.x + threadIdx.x;   // 0..16383
    const int d = idx & (DDIM - 1);
    const float LOG2E = 1.4426950408889634f;
    const float dgl = __ldg(&d_g[d]) * LOG2E;
    const float bgl = __ldg(&b_g[d]) * LOG2E;

    float* houtp = out + (size_t)TT * SBD;   // h buffer [T+1, B, D]
    houtp[idx] = 0.0f;                       // h0

    const float* A = g_alpha;
    const float* V = g_vraw;

    constexpr int PF = 8;
    float pa[PF], pv[PF];
#pragma unroll
    for (int i = 0; i < PF; i++) {
        pa[i] = __ldg(&A[(size_t)i * SBD + idx]);
        pv[i] = __ldg(&V[(size_t)i * SBD + idx]);
    }

    float h = 0.0f;
#pragma unroll 1
    for (int t0 = 0; t0 < TT; t0 += PF) {
        float ca[PF], cv[PF];
#pragma unroll
        for (int i = 0; i < PF; i++) { ca[i] = pa[i]; cv[i] = pv[i]; }
        const int tn = t0 + PF;
        if (tn < TT) {
#pragma unroll
            for (int i = 0; i < PF; i++) {
                pa[i] = __ldg(&A[(size_t)(tn + i) * SBD + idx]);
                pv[i] = __ldg(&V[(size_t)(tn + i) * SBD + idx]);
            }
        }
#pragma unroll
        for (int i = 0; i < PF; i++) {
            const float a = ca[i];
            const float c = (1.0f - a) * cv[i];        // off critical chain
            const float ah = a * h;                    // parallel with g-chain
            const float ex = exp2f(fmaf(dgl, fabsf(h), -bgl));
            const float g = __fdividef(1.0f, 1.0f + ex);
            h = fmaf(c, g, ah);                        // h_new
            const float sg = __fdividef(1.0f, 1.0f + exp2f(-h * LOG2E));
            const size_t t = (size_t)(t0 + i);
            out[t * SBD + idx] = h * h * sg;           // h * silu(h)
            houtp[(t + 1) * SBD + idx] = h;
        }
    }
}

// ---------------- launcher ----------------
extern "C" void kernel_launch(void* const* d_in, const int* in_sizes, int n_in,
                              void* d_out, int out_size) {
    const float* x       = (const float*)d_in[0];
    const float* W_alpha = (const float*)d_in[1];
    const float* b_alpha = (const float*)d_in[2];
    const float* d_g     = (const float*)d_in[3];
    const float* b_g     = (const float*)d_in[4];
    const float* W_x     = (const float*)d_in[5];
    const float* b_v     = (const float*)d_in[6];
    float* out = (float*)d_out;

    (void)in_sizes; (void)n_in; (void)out_size;

    cudaFuncSetAttribute(gemm_kernel, cudaFuncAttributeMaxDynamicSharedMemorySize,
                         SMEM_GEMM_TOTAL);

    // 1) split fp32 -> bf16 hi/lo
    {
        const int n4 = (int)(NELEM / 4);
        split_x_kernel<<<(n4 + 255) / 256, 256>>>(x);
        const int w4 = 2 * DDIM * DDIM / 4;
        split_w_kernel<<<(w4 + 255) / 256, 256>>>(W_alpha, W_x);
    }

    // 2) dual fused GEMM + activation epilogue (z=0: sigmoid/alpha, z=1: tanh/vraw)
    {
        dim3 grid(DDIM / 256, MM / 128, 2);
        gemm_kernel<<<grid, 512, SMEM_GEMM_TOTAL>>>(b_alpha, b_v);
    }

    // 3) sequential scan, fully parallel over B*D lanes
    scan_kernel<<<SBD / 128, 128>>>(d_g, b_g, out);
}

// round 4
// speedup vs baseline: 1.0777x; 1.0777x over previous
#include <cuda_runtime.h>
#include <cuda_bf16.h>
#include <cstdint>

// ---------------- problem dims ----------------
#define TT 2048
#define BB 16
#define DDIM 1024
#define MM (TT*BB)            // 32768 rows
#define SBD (BB*DDIM)         // 16384 lanes in scan
#define NELEM ((size_t)MM*DDIM)

// ---------------- device scratch (no cudaMalloc allowed) ----------------
__device__ __nv_bfloat16 g_xhi[NELEM];
__device__ __nv_bfloat16 g_xlo[NELEM];
__device__ __nv_bfloat16 g_whi[2*DDIM*DDIM];
__device__ __nv_bfloat16 g_wlo[2*DDIM*DDIM];
__device__ float g_alpha[NELEM];
__device__ float g_vraw[NELEM];

// ---------------- PTX helpers (base sm_103 target only: no tcgen05/TMA) ----
__device__ __forceinline__ uint32_t smem_u32(const void* p) {
    uint32_t a;
    asm("{ .reg .u64 t; cvta.to.shared.u64 t, %1; cvt.u32.u64 %0, t; }" : "=r"(a) : "l"(p));
    return a;
}
__device__ __forceinline__ void cp16(uint32_t s, const void* g) {
    asm volatile("cp.async.cg.shared.global [%0], [%1], 16;" :: "r"(s), "l"(g));
}
__device__ __forceinline__ void cp_commit() {
    asm volatile("cp.async.commit_group;" ::: "memory");
}
template <int N>
__device__ __forceinline__ void cp_wait() {
    asm volatile("cp.async.wait_group %0;" :: "n"(N) : "memory");
}
__device__ __forceinline__ void ldsm4(uint32_t* r, uint32_t addr) {
    asm volatile("ldmatrix.sync.aligned.m8n8.x4.shared.b16 {%0,%1,%2,%3}, [%4];"
                 : "=r"(r[0]), "=r"(r[1]), "=r"(r[2]), "=r"(r[3]) : "r"(addr));
}
__device__ __forceinline__ void mma16816(float* c, const uint32_t* a, const uint32_t* b) {
    asm volatile("mma.sync.aligned.m16n8k16.row.col.f32.bf16.bf16.f32 "
                 "{%0,%1,%2,%3}, {%4,%5,%6,%7}, {%8,%9}, {%0,%1,%2,%3};"
                 : "+f"(c[0]), "+f"(c[1]), "+f"(c[2]), "+f"(c[3])
                 : "r"(a[0]), "r"(a[1]), "r"(a[2]), "r"(a[3]), "r"(b[0]), "r"(b[1]));
}

// ---------------- split kernels (fp32 -> bf16 hi/lo) ----------------
__global__ void split_x_kernel(const float* __restrict__ x) {
    size_t i = (size_t)blockIdx.x * blockDim.x + threadIdx.x;  // float4 index
    if (i >= NELEM / 4) return;
    float4 v = reinterpret_cast<const float4*>(x)[i];
    union { __nv_bfloat16 b[4]; uint2 u; } H, L;
    float f[4] = {v.x, v.y, v.z, v.w};
#pragma unroll
    for (int j = 0; j < 4; j++) {
        __nv_bfloat16 h = __float2bfloat16(f[j]);
        H.b[j] = h;
        L.b[j] = __float2bfloat16(f[j] - __bfloat162float(h));
    }
    reinterpret_cast<uint2*>(g_xhi)[i] = H.u;
    reinterpret_cast<uint2*>(g_xlo)[i] = L.u;
}

__global__ void split_w_kernel(const float* __restrict__ Wa, const float* __restrict__ Wx) {
    size_t i = (size_t)blockIdx.x * blockDim.x + threadIdx.x;  // float4 index over 2 matrices
    const size_t nper = (size_t)DDIM * DDIM / 4;
    if (i >= 2 * nper) return;
    const float* src = (i < nper) ? Wa : Wx;
    size_t j = (i < nper) ? i : i - nper;
    float4 v = reinterpret_cast<const float4*>(src)[j];
    union { __nv_bfloat16 b[4]; uint2 u; } H, L;
    float f[4] = {v.x, v.y, v.z, v.w};
#pragma unroll
    for (int k = 0; k < 4; k++) {
        __nv_bfloat16 h = __float2bfloat16(f[k]);
        H.b[k] = h;
        L.b[k] = __float2bfloat16(f[k] - __bfloat162float(h));
    }
    reinterpret_cast<uint2*>(g_whi)[i] = H.u;
    reinterpret_cast<uint2*>(g_wlo)[i] = L.u;
}

// ---------------- GEMM: out[m,e] = act( sum_d x[m,d]*W[e,d] + bias[e] ) ------
// bf16x3 via mma.sync m16n8k16 (HMMA). CTA tile 128x256x32, 256 thr (8 warps,
// warp tile 64x64), 3-stage cp.async ring, one __syncthreads per k-chunk.
static constexpr int BK       = 32;
static constexpr int ROWB     = 80;          // padded row bytes (32 bf16 + 16B pad)
static constexpr int A_TILE_B = 128 * ROWB;  // 10240
static constexpr int B_TILE_B = 256 * ROWB;  // 20480
static constexpr int ST_AHI = 0;
static constexpr int ST_ALO = ST_AHI + A_TILE_B;
static constexpr int ST_BHI = ST_ALO + A_TILE_B;
static constexpr int ST_BLO = ST_BHI + B_TILE_B;
static constexpr int STAGE_B  = ST_BLO + B_TILE_B;          // 61440
static constexpr int NSTAGE   = 3;
static constexpr int SMEM_GEMM_TOTAL = NSTAGE * STAGE_B;    // 184320
static constexpr int NKC      = DDIM / BK;                  // 32

__global__ void __launch_bounds__(256, 1)
gemm_kernel(const float* __restrict__ b_alpha, const float* __restrict__ b_v) {
    extern __shared__ char smem[];
    const uint32_t sbase = smem_u32(smem);
    const int tid = threadIdx.x;
    const int wid = tid >> 5;
    const int l   = tid & 31;
    const int wid_m = wid >> 2;      // 0..1  (64-row slabs)
    const int wid_n = wid & 3;       // 0..3  (64-col slabs)
    const int bn = blockIdx.x;       // 0..3   (N tiles of 256)
    const int bm = blockIdx.y;       // 0..255 (M tiles of 128)
    const int ws = blockIdx.z;       // 0: alpha, 1: vraw

    const __nv_bfloat16* __restrict__ Ahi_g = g_xhi + (size_t)bm * 128 * DDIM;
    const __nv_bfloat16* __restrict__ Alo_g = g_xlo + (size_t)bm * 128 * DDIM;
    const __nv_bfloat16* __restrict__ Bhi_g = g_whi + (size_t)ws * DDIM * DDIM + (size_t)bn * 256 * DDIM;
    const __nv_bfloat16* __restrict__ Blo_g = g_wlo + (size_t)ws * DDIM * DDIM + (size_t)bn * 256 * DDIM;
    float* __restrict__ outp = ws ? g_vraw : g_alpha;
    const float* __restrict__ bias = ws ? b_v : b_alpha;

    // cp.async mapping: 256 threads; A tiles 512 chunks (2/thread), B tiles 1024 (4/thread)
    const int crow = tid >> 2;       // 0..63
    const int cseg = tid & 3;        // 0..3 (16B chunk within 64B row)

    auto issue_stage = [&](int stage, int kc) {
        const uint32_t s0 = sbase + stage * STAGE_B;
        const size_t kel = (size_t)kc * BK + cseg * 8;
        const uint32_t so = cseg * 16;
#pragma unroll
        for (int r2 = 0; r2 < 2; r2++) {
            const int r = crow + r2 * 64;
            cp16(s0 + ST_AHI + r * ROWB + so, Ahi_g + (size_t)r * DDIM + kel);
            cp16(s0 + ST_ALO + r * ROWB + so, Alo_g + (size_t)r * DDIM + kel);
        }
#pragma unroll
        for (int r4 = 0; r4 < 4; r4++) {
            const int r = crow + r4 * 64;
            cp16(s0 + ST_BHI + r * ROWB + so, Bhi_g + (size_t)r * DDIM + kel);
            cp16(s0 + ST_BLO + r * ROWB + so, Blo_g + (size_t)r * DDIM + kel);
        }
        cp_commit();
    };

    // ldmatrix lane-address components
    const uint32_t a_lane_off = (uint32_t)((l & 15) * ROWB + (l >> 4) * 16);
    const uint32_t b_lane_off = (uint32_t)(((l & 7) + ((l >> 4) << 3)) * ROWB + ((l >> 3) & 1) * 16);

    float acc[4][8][4];
#pragma unroll
    for (int mi = 0; mi < 4; mi++)
#pragma unroll
        for (int ni = 0; ni < 8; ni++)
#pragma unroll
            for (int r = 0; r < 4; r++) acc[mi][ni][r] = 0.0f;

    issue_stage(0, 0);
    issue_stage(1, 1);

    int rd = 0, wr = 2;
#pragma unroll 1
    for (int kc = 0; kc < NKC; kc++) {
        if (kc + 1 < NKC) cp_wait<1>(); else cp_wait<0>();
        __syncthreads();
        if (kc + 2 < NKC) issue_stage(wr, kc + 2);

        const uint32_t s0 = sbase + rd * STAGE_B;
        const uint32_t sAhi = s0 + ST_AHI + (uint32_t)(wid_m * 64 * ROWB) + a_lane_off;
        const uint32_t sAlo = s0 + ST_ALO + (uint32_t)(wid_m * 64 * ROWB) + a_lane_off;
        const uint32_t sBhi = s0 + ST_BHI + (uint32_t)(wid_n * 64 * ROWB) + b_lane_off;
        const uint32_t sBlo = s0 + ST_BLO + (uint32_t)(wid_n * 64 * ROWB) + b_lane_off;

#pragma unroll
        for (int ks = 0; ks < 2; ks++) {
            uint32_t bh[4][4], bl[4][4];
#pragma unroll
            for (int ni2 = 0; ni2 < 4; ni2++) {
                ldsm4(bh[ni2], sBhi + ni2 * 16 * ROWB + ks * 32);
                ldsm4(bl[ni2], sBlo + ni2 * 16 * ROWB + ks * 32);
            }
#pragma unroll
            for (int mi = 0; mi < 4; mi++) {
                uint32_t ah[4], al[4];
                ldsm4(ah, sAhi + mi * 16 * ROWB + ks * 32);
                ldsm4(al, sAlo + mi * 16 * ROWB + ks * 32);
#pragma unroll
                for (int n8 = 0; n8 < 8; n8++) {
                    const uint32_t* bhp = &bh[n8 >> 1][(n8 & 1) * 2];
                    const uint32_t* blp = &bl[n8 >> 1][(n8 & 1) * 2];
                    mma16816(acc[mi][n8], ah, bhp);
                    mma16816(acc[mi][n8], ah, blp);
                    mma16816(acc[mi][n8], al, bhp);
                }
            }
        }
        rd = (rd + 1 == NSTAGE) ? 0 : rd + 1;
        wr = (wr + 1 == NSTAGE) ? 0 : wr + 1;
    }

    // epilogue: bias + activation, direct float2 stores
    const int row_base = bm * 128 + wid_m * 64 + (l >> 2);
    const int col_base = bn * 256 + wid_n * 64 + (l & 3) * 2;
#pragma unroll
    for (int mi = 0; mi < 4; mi++) {
#pragma unroll
        for (int n8 = 0; n8 < 8; n8++) {
            const int col = col_base + n8 * 8;
            const float bia0 = __ldg(&bias[col]);
            const float bia1 = __ldg(&bias[col + 1]);
#pragma unroll
            for (int half = 0; half < 2; half++) {
                const int row = row_base + mi * 16 + half * 8;
                float v0 = acc[mi][n8][half * 2 + 0] + bia0;
                float v1 = acc[mi][n8][half * 2 + 1] + bia1;
                float2 o;
                if (ws) { o.x = tanhf(v0); o.y = tanhf(v1); }
                else {
                    o.x = __fdividef(1.0f, 1.0f + __expf(-v0));
                    o.y = __fdividef(1.0f, 1.0f + __expf(-v1));
                }
                *reinterpret_cast<float2*>(outp + (size_t)row * DDIM + col) = o;
            }
        }
    }
}

// ---------------- scan kernel: 16384 independent recurrences over T ----------
// 32-thread blocks spread 512 warps across all SMSPs. Two 8-deep prefetch
// buffers give a 16-step load lead (> DRAM latency).
__global__ void __launch_bounds__(32)
scan_kernel(const float* __restrict__ d_g, const float* __restrict__ b_g,
            float* __restrict__ out) {
    const int idx = blockIdx.x * 32 + threadIdx.x;   // 0..16383
    const int d = idx & (DDIM - 1);
    const float LOG2E = 1.4426950408889634f;
    const float dgl = __ldg(&d_g[d]) * LOG2E;
    const float bgl = __ldg(&b_g[d]) * LOG2E;

    float* houtp = out + (size_t)TT * SBD;   // h buffer [T+1, B, D]
    houtp[idx] = 0.0f;                       // h0

    const float* A = g_alpha;
    const float* V = g_vraw;

    float paA[8], pvA[8], paB[8], pvB[8];
#pragma unroll
    for (int i = 0; i < 8; i++) {
        paA[i] = __ldg(&A[(size_t)i * SBD + idx]);
        pvA[i] = __ldg(&V[(size_t)i * SBD + idx]);
        paB[i] = __ldg(&A[(size_t)(i + 8) * SBD + idx]);
        pvB[i] = __ldg(&V[(size_t)(i + 8) * SBD + idx]);
    }

    float h = 0.0f;

#define SCAN8(CA, CV, TBASE)                                                    \
    do {                                                                        \
        _Pragma("unroll")                                                       \
        for (int i = 0; i < 8; i++) {                                           \
            const float a = CA[i];                                              \
            const float c = (1.0f - a) * CV[i];                                 \
            const float ah = a * h;                                             \
            const float ex = exp2f(fmaf(dgl, fabsf(h), -bgl));                  \
            const float g = __fdividef(1.0f, 1.0f + ex);                        \
            h = fmaf(c, g, ah);                                                 \
            const float sg = __fdividef(1.0f, 1.0f + exp2f(-h * LOG2E));        \
            const size_t t = (size_t)((TBASE) + i);                             \
            out[t * SBD + idx] = h * h * sg;                                    \
            houtp[(t + 1) * SBD + idx] = h;                                     \
        }                                                                       \
    } while (0)

#pragma unroll 1
    for (int t0 = 0; t0 < TT; t0 += 16) {
        float ca[8], cv[8];
#pragma unroll
        for (int i = 0; i < 8; i++) { ca[i] = paA[i]; cv[i] = pvA[i]; }
        if (t0 + 16 < TT) {
#pragma unroll
            for (int i = 0; i < 8; i++) {
                paA[i] = __ldg(&A[(size_t)(t0 + 16 + i) * SBD + idx]);
                pvA[i] = __ldg(&V[(size_t)(t0 + 16 + i) * SBD + idx]);
            }
        }
        SCAN8(ca, cv, t0);

#pragma unroll
        for (int i = 0; i < 8; i++) { ca[i] = paB[i]; cv[i] = pvB[i]; }
        if (t0 + 24 < TT) {
#pragma unroll
            for (int i = 0; i < 8; i++) {
                paB[i] = __ldg(&A[(size_t)(t0 + 24 + i) * SBD + idx]);
                pvB[i] = __ldg(&V[(size_t)(t0 + 24 + i) * SBD + idx]);
            }
        }
        SCAN8(ca, cv, t0 + 8);
    }
#undef SCAN8
}

// ---------------- launcher ----------------
extern "C" void kernel_launch(void* const* d_in, const int* in_sizes, int n_in,
                              void* d_out, int out_size) {
    const float* x       = (const float*)d_in[0];
    const float* W_alpha = (const float*)d_in[1];
    const float* b_alpha = (const float*)d_in[2];
    const float* d_g     = (const float*)d_in[3];
    const float* b_g     = (const float*)d_in[4];
    const float* W_x     = (const float*)d_in[5];
    const float* b_v     = (const float*)d_in[6];
    float* out = (float*)d_out;

    (void)in_sizes; (void)n_in; (void)out_size;

    cudaFuncSetAttribute(gemm_kernel, cudaFuncAttributeMaxDynamicSharedMemorySize,
                         SMEM_GEMM_TOTAL);

    // 1) split fp32 -> bf16 hi/lo
    {
        const int n4 = (int)(NELEM / 4);
        split_x_kernel<<<(n4 + 255) / 256, 256>>>(x);
        const int w4 = 2 * DDIM * DDIM / 4;
        split_w_kernel<<<(w4 + 255) / 256, 256>>>(W_alpha, W_x);
    }

    // 2) dual fused GEMM + activation epilogue (z=0: sigmoid/alpha, z=1: tanh/vraw)
    {
        dim3 grid(DDIM / 256, MM / 128, 2);
        gemm_kernel<<<grid, 256, SMEM_GEMM_TOTAL>>>(b_alpha, b_v);
    }

    // 3) sequential scan, fully parallel over B*D lanes
    scan_kernel<<<SBD / 32, 32>>>(d_g, b_g, out);
}